// round 2
// baseline (speedup 1.0000x reference)
#include <cuda_runtime.h>
#include <math.h>

#define N_NODES 8192
#define NFEAT   256
#define NHID    64
#define NHEADS  4
#define DHID    (NHEADS*NHID)   /* 256 */
#define NCLASS  121
#define LDC2    128             /* padded ld for Whc */
#define MAXDEG  512
#define LRELU_ALPHA 0.2f

/* ---------------- scratch (static device globals; no allocs) -------------- */
__device__ float g_Wh[N_NODES * DHID];        /* 8 MB  layer-1 Wh, heads concat */
__device__ float g_Wcat[NFEAT * DHID];        /* 256 KB packed W */
__device__ float g_fs[NHEADS * N_NODES];
__device__ float g_fd[NHEADS * N_NODES];
__device__ float g_hcat[N_NODES * DHID];      /* 8 MB layer-1 output */
__device__ float g_Whc[N_NODES * LDC2];       /* 4 MB layer-2 Wh (ld=128) */
__device__ float g_f2s[N_NODES];
__device__ float g_f2d[N_NODES];
__device__ int   g_cols[(size_t)N_NODES * MAXDEG];  /* 16 MB edge lists */
__device__ int   g_deg[N_NODES];

/* ---------------- 1. build per-row edge lists (one pass over adj) --------- */
/* block = one row, 256 threads; each thread owns a contiguous 32-elem segment.
   Segmented count -> block inclusive scan -> ordered fill. Deterministic. */
__global__ void build_edges(const float* __restrict__ adj) {
    int row = blockIdx.x;
    int tid = threadIdx.x;
    const float4* a4 = (const float4*)(adj + (size_t)row * N_NODES + tid * 32);

    float4 v[8];
    int cnt = 0;
#pragma unroll
    for (int q = 0; q < 8; q++) {
        v[q] = a4[q];
        cnt += (v[q].x > 0.f) + (v[q].y > 0.f) + (v[q].z > 0.f) + (v[q].w > 0.f);
    }

    __shared__ int s[256];
    s[tid] = cnt;
    __syncthreads();
    for (int off = 1; off < 256; off <<= 1) {
        int t = (tid >= off) ? s[tid - off] : 0;
        __syncthreads();
        s[tid] += t;
        __syncthreads();
    }
    int pos = s[tid] - cnt;            /* exclusive prefix */
    if (tid == 0) {
        int total = s[255];
        g_deg[row] = total < MAXDEG ? total : MAXDEG;
    }

    int* outc = g_cols + (size_t)row * MAXDEG;
#pragma unroll
    for (int q = 0; q < 8; q++) {
        int base = tid * 32 + q * 4;
        if (v[q].x > 0.f) { if (pos < MAXDEG) outc[pos] = base + 0; pos++; }
        if (v[q].y > 0.f) { if (pos < MAXDEG) outc[pos] = base + 1; pos++; }
        if (v[q].z > 0.f) { if (pos < MAXDEG) outc[pos] = base + 2; pos++; }
        if (v[q].w > 0.f) { if (pos < MAXDEG) outc[pos] = base + 3; pos++; }
    }
}

/* ---------------- 2. pack Ws [H,256,64] -> Wcat [256, 256] ---------------- */
__global__ void pack_W(const float* __restrict__ Ws) {
    int idx = blockIdx.x * blockDim.x + threadIdx.x;   /* 65536 */
    int n = idx & 255;          /* output col = h*64+c */
    int k = idx >> 8;           /* input row */
    int h = n >> 6, c = n & 63;
    g_Wcat[k * DHID + n] = Ws[((size_t)h * NFEAT + k) * NHID + c];
}

/* ---------------- 3. SGEMM: C[M,N] = A[M,K] * B[K,N] --------------------- */
/* BM=128, BN=64, BK=8, 256 threads, 8x4 register tile. M%128==0, K%8==0.   */
__global__ void sgemm(const float* __restrict__ A, const float* __restrict__ B,
                      float* __restrict__ C, int M, int N, int K, int ldc) {
    __shared__ float As[8][128];
    __shared__ float Bs[8][64];
    int tid = threadIdx.x;
    int tx = tid & 15, ty = tid >> 4;
    int row0 = blockIdx.y * 128;
    int col0 = blockIdx.x * 64;

    float acc[8][4];
#pragma unroll
    for (int i = 0; i < 8; i++)
#pragma unroll
        for (int j = 0; j < 4; j++) acc[i][j] = 0.f;

    int a_r = tid >> 1;              /* 0..127 */
    int a_c = (tid & 1) * 4;         /* 0 or 4 */
    int b_r = tid >> 5;              /* 0..7   */
    int b_c = (tid & 31) * 2;        /* 0..62  */

    for (int k0 = 0; k0 < K; k0 += 8) {
        float4 av = *(const float4*)(A + (size_t)(row0 + a_r) * K + k0 + a_c);
        As[a_c + 0][a_r] = av.x;
        As[a_c + 1][a_r] = av.y;
        As[a_c + 2][a_r] = av.z;
        As[a_c + 3][a_r] = av.w;
        int bc = col0 + b_c;
        Bs[b_r][b_c]     = (bc     < N) ? B[(size_t)(k0 + b_r) * N + bc]     : 0.f;
        Bs[b_r][b_c + 1] = (bc + 1 < N) ? B[(size_t)(k0 + b_r) * N + bc + 1] : 0.f;
        __syncthreads();
#pragma unroll
        for (int kk = 0; kk < 8; kk++) {
            float4 ra0 = *(const float4*)&As[kk][ty * 8];
            float4 ra1 = *(const float4*)&As[kk][ty * 8 + 4];
            float4 rb  = *(const float4*)&Bs[kk][tx * 4];
            float ra[8] = {ra0.x, ra0.y, ra0.z, ra0.w, ra1.x, ra1.y, ra1.z, ra1.w};
            float rbv[4] = {rb.x, rb.y, rb.z, rb.w};
#pragma unroll
            for (int i = 0; i < 8; i++)
#pragma unroll
                for (int j = 0; j < 4; j++)
                    acc[i][j] += ra[i] * rbv[j];
        }
        __syncthreads();
    }
#pragma unroll
    for (int i = 0; i < 8; i++) {
        int r = row0 + ty * 8 + i;
#pragma unroll
        for (int j = 0; j < 4; j++) {
            int c = col0 + tx * 4 + j;
            if (c < N) C[(size_t)r * ldc + c] = acc[i][j];
        }
    }
}

/* ---------------- 4. layer-1 attention scores f_src/f_dst ----------------- */
__global__ void f1_kernel(const float* __restrict__ a_heads) {
    int row = blockIdx.x, tid = threadIdx.x;
    int h = tid >> 6, c = tid & 63;
    float v = g_Wh[(size_t)row * DHID + tid];
    float vs = v * a_heads[h * (2 * NHID) + c];
    float vd = v * a_heads[h * (2 * NHID) + NHID + c];
#pragma unroll
    for (int o = 16; o > 0; o >>= 1) {
        vs += __shfl_xor_sync(0xffffffffu, vs, o);
        vd += __shfl_xor_sync(0xffffffffu, vd, o);
    }
    __shared__ float ss[8], sd[8];
    int w = tid >> 5;
    if ((tid & 31) == 0) { ss[w] = vs; sd[w] = vd; }
    __syncthreads();
    if ((tid & 63) == 0) {
        g_fs[h * N_NODES + row] = ss[w] + ss[w + 1];
        g_fd[h * N_NODES + row] = sd[w] + sd[w + 1];
    }
}

/* ---------------- 5. layer-1 softmax-aggregate + ELU --------------------- */
/* block = one row; 256 threads = 4 head-groups of 64; f = tid&63.          */
__global__ void agg1() {
    int row = blockIdx.x, tid = threadIdx.x;
    int h = tid >> 6, f = tid & 63;
    __shared__ int   s_col[MAXDEG];
    __shared__ float s_w[NHEADS][MAXDEG];
    __shared__ float s_rmax[8], s_rsum[8];
    __shared__ float s_m[NHEADS], s_d[NHEADS];

    int deg = g_deg[row];
    for (int k = tid; k < deg; k += 256)
        s_col[k] = g_cols[(size_t)row * MAXDEG + k];
    __syncthreads();

    float fsi = g_fs[h * N_NODES + row];
    const float* fdh = g_fd + h * N_NODES;

    /* pass A: e = lrelu(fs+fd), running max */
    float m = -1e30f;
    for (int k = f; k < deg; k += 64) {
        float e = fsi + fdh[s_col[k]];
        e = (e > 0.f) ? e : LRELU_ALPHA * e;
        s_w[h][k] = e;
        m = fmaxf(m, e);
    }
#pragma unroll
    for (int o = 16; o > 0; o >>= 1) m = fmaxf(m, __shfl_xor_sync(0xffffffffu, m, o));
    int w = tid >> 5;
    if ((tid & 31) == 0) s_rmax[w] = m;
    __syncthreads();
    if (f == 0) s_m[h] = fmaxf(s_rmax[2 * h], s_rmax[2 * h + 1]);
    __syncthreads();
    float mh = s_m[h];

    /* pass B: w = exp(e-m), sum */
    float lsum = 0.f;
    for (int k = f; k < deg; k += 64) {
        float wv = expf(s_w[h][k] - mh);
        s_w[h][k] = wv;
        lsum += wv;
    }
#pragma unroll
    for (int o = 16; o > 0; o >>= 1) lsum += __shfl_xor_sync(0xffffffffu, lsum, o);
    if ((tid & 31) == 0) s_rsum[w] = lsum;
    __syncthreads();
    if (f == 0) s_d[h] = s_rsum[2 * h] + s_rsum[2 * h + 1];
    __syncthreads();
    float inv = 1.f / s_d[h];

    /* pass C: weighted gather over neighbors */
    float acc = 0.f;
    int base = h * NHID + f;
#pragma unroll 4
    for (int k = 0; k < deg; k++) {
        acc += s_w[h][k] * g_Wh[(size_t)s_col[k] * DHID + base];
    }
    acc *= inv;
    acc = (acc > 0.f) ? acc : expm1f(acc);       /* ELU (concat=True) */
    g_hcat[(size_t)row * DHID + tid] = acc;
}

/* ---------------- 6. layer-2 attention scores ----------------------------- */
__global__ void f2_kernel(const float* __restrict__ a_out) {
    int row = blockIdx.x, tid = threadIdx.x;     /* 128 threads */
    float vs = 0.f, vd = 0.f;
    if (tid < NCLASS) {
        float v = g_Whc[(size_t)row * LDC2 + tid];
        vs = v * a_out[tid];
        vd = v * a_out[NCLASS + tid];
    }
#pragma unroll
    for (int o = 16; o > 0; o >>= 1) {
        vs += __shfl_xor_sync(0xffffffffu, vs, o);
        vd += __shfl_xor_sync(0xffffffffu, vd, o);
    }
    __shared__ float ss[4], sd[4];
    int w = tid >> 5;
    if ((tid & 31) == 0) { ss[w] = vs; sd[w] = vd; }
    __syncthreads();
    if (tid == 0) {
        g_f2s[row] = ss[0] + ss[1] + ss[2] + ss[3];
        g_f2d[row] = sd[0] + sd[1] + sd[2] + sd[3];
    }
}

/* ---------------- 7. layer-2 softmax-aggregate (no ELU) ------------------- */
__global__ void agg2(float* __restrict__ out) {
    int row = blockIdx.x, tid = threadIdx.x;     /* 128 threads */
    __shared__ int   s_col[MAXDEG];
    __shared__ float s_w[MAXDEG];
    __shared__ float s_rmax[4], s_rsum[4];
    __shared__ float s_m, s_den;

    int deg = g_deg[row];
    for (int k = tid; k < deg; k += 128)
        s_col[k] = g_cols[(size_t)row * MAXDEG + k];
    __syncthreads();

    float fsi = g_f2s[row];
    float m = -1e30f;
    for (int k = tid; k < deg; k += 128) {
        float e = fsi + g_f2d[s_col[k]];
        e = (e > 0.f) ? e : LRELU_ALPHA * e;
        s_w[k] = e;
        m = fmaxf(m, e);
    }
#pragma unroll
    for (int o = 16; o > 0; o >>= 1) m = fmaxf(m, __shfl_xor_sync(0xffffffffu, m, o));
    int w = tid >> 5;
    if ((tid & 31) == 0) s_rmax[w] = m;
    __syncthreads();
    if (tid == 0) s_m = fmaxf(fmaxf(s_rmax[0], s_rmax[1]), fmaxf(s_rmax[2], s_rmax[3]));
    __syncthreads();
    float mh = s_m;

    float lsum = 0.f;
    for (int k = tid; k < deg; k += 128) {
        float wv = expf(s_w[k] - mh);
        s_w[k] = wv;
        lsum += wv;
    }
#pragma unroll
    for (int o = 16; o > 0; o >>= 1) lsum += __shfl_xor_sync(0xffffffffu, lsum, o);
    if ((tid & 31) == 0) s_rsum[w] = lsum;
    __syncthreads();
    if (tid == 0) s_den = s_rsum[0] + s_rsum[1] + s_rsum[2] + s_rsum[3];
    __syncthreads();
    float inv = 1.f / s_den;

    if (tid < NCLASS) {
        float acc = 0.f;
#pragma unroll 4
        for (int k = 0; k < deg; k++)
            acc += s_w[k] * g_Whc[(size_t)s_col[k] * LDC2 + tid];
        out[(size_t)row * NCLASS + tid] = acc * inv;
    }
}

/* ---------------- launch ------------------------------------------------- */
extern "C" void kernel_launch(void* const* d_in, const int* in_sizes, int n_in,
                              void* d_out, int out_size) {
    const float* x       = (const float*)d_in[0];   /* [8192,256]  */
    const float* adj     = (const float*)d_in[1];   /* [8192,8192] */
    const float* Ws      = (const float*)d_in[2];   /* [4,256,64]  */
    const float* a_heads = (const float*)d_in[3];   /* [4,128]     */
    const float* W_out   = (const float*)d_in[4];   /* [256,121]   */
    const float* a_out   = (const float*)d_in[5];   /* [242]       */
    float* out = (float*)d_out;                     /* [8192,121]  */

    float* p_Wh;   cudaGetSymbolAddress((void**)&p_Wh,   g_Wh);
    float* p_Wcat; cudaGetSymbolAddress((void**)&p_Wcat, g_Wcat);
    float* p_hcat; cudaGetSymbolAddress((void**)&p_hcat, g_hcat);
    float* p_Whc;  cudaGetSymbolAddress((void**)&p_Whc,  g_Whc);

    build_edges<<<N_NODES, 256>>>(adj);
    pack_W<<<NFEAT * DHID / 256, 256>>>(Ws);
    {
        dim3 grid(DHID / 64, N_NODES / 128);
        sgemm<<<grid, 256>>>(x, p_Wcat, p_Wh, N_NODES, DHID, NFEAT, DHID);
    }
    f1_kernel<<<N_NODES, 256>>>(a_heads);
    agg1<<<N_NODES, 256>>>();
    {
        dim3 grid((NCLASS + 63) / 64, N_NODES / 128);
        sgemm<<<grid, 256>>>(p_hcat, W_out, p_Whc, N_NODES, NCLASS, DHID, LDC2);
    }
    f2_kernel<<<N_NODES, 128>>>(a_out);
    agg2<<<N_NODES, 128>>>(out);
}